// round 3
// baseline (speedup 1.0000x reference)
#include <cuda_runtime.h>
#include <math_constants.h>

#define THREADS 256
#define SEG 8192              // elements per block in quant/output passes
#define MAXB 4096
#define NELEM_MAX (1 << 24)   // 1*32*4096*128 = 2^24

// ---------------- device scratch (no allocations allowed) ----------------
__device__ unsigned int d_umin = 0xFFFFFFFFu;   // re-armed at end of k_output
__device__ unsigned int d_umax = 0u;
__device__ int d_hist[256];                     // zeroed at end of k_select
__device__ int d_bhT[256][MAXB];                // bin-major per-block histogram
__device__ unsigned char d_qbuf[NELEM_MAX];
__device__ int d_t, d_r;
__device__ int d_tieoff[MAXB];

// order-preserving float <-> uint mapping for atomic min/max
__device__ __forceinline__ unsigned int enc_f(float f) {
    unsigned int u = __float_as_uint(f);
    return (u & 0x80000000u) ? ~u : (u | 0x80000000u);
}
__device__ __forceinline__ float dec_f(unsigned int e) {
    unsigned int u = (e & 0x80000000u) ? (e & 0x7FFFFFFFu) : ~e;
    return __uint_as_float(u);
}

// exact quantization matching jnp: ((x-min)/range)*255, round-half-even
__device__ __forceinline__ int quant(float v, float minv, float range) {
    float n = __fdiv_rn(v - minv, range);       // IEEE divide (no fast-math)
    float s = __fmul_rn(n, 255.0f);             // IEEE multiply
    int q = (int)rintf(s);                      // RNE, same as jnp.round
    return min(255, max(0, q));
}

// ---------------- pass 1: global min/max ----------------
__global__ void k_minmax(const float* __restrict__ x, int n) {
    float lmin = CUDART_INF_F, lmax = -CUDART_INF_F;
    int n4 = n >> 2;
    const float4* x4 = reinterpret_cast<const float4*>(x);
    for (int i = blockIdx.x * blockDim.x + threadIdx.x; i < n4;
         i += gridDim.x * blockDim.x) {
        float4 v = x4[i];
        lmin = fminf(lmin, fminf(fminf(v.x, v.y), fminf(v.z, v.w)));
        lmax = fmaxf(lmax, fmaxf(fmaxf(v.x, v.y), fmaxf(v.z, v.w)));
    }
    if (blockIdx.x == 0) {  // scalar tail
        for (int i = n4 * 4 + threadIdx.x; i < n; i += blockDim.x) {
            float v = x[i];
            lmin = fminf(lmin, v);
            lmax = fmaxf(lmax, v);
        }
    }
#pragma unroll
    for (int o = 16; o; o >>= 1) {
        lmin = fminf(lmin, __shfl_xor_sync(0xFFFFFFFFu, lmin, o));
        lmax = fmaxf(lmax, __shfl_xor_sync(0xFFFFFFFFu, lmax, o));
    }
    __shared__ float smin[8], smax[8];
    int lane = threadIdx.x & 31, wid = threadIdx.x >> 5;
    if (lane == 0) { smin[wid] = lmin; smax[wid] = lmax; }
    __syncthreads();
    if (threadIdx.x == 0) {
#pragma unroll
        for (int w = 1; w < 8; w++) {
            lmin = fminf(lmin, smin[w]);
            lmax = fmaxf(lmax, smax[w]);
        }
        atomicMin(&d_umin, enc_f(lmin));
        atomicMax(&d_umax, enc_f(lmax));
    }
}

// ---------------- pass 2: quantize + per-block histogram ----------------
__global__ void k_quanthist(const float* __restrict__ x, int n) {
    __shared__ int sh[8][256];   // per-warp sub-histograms (8 KB)
    int tid = threadIdx.x;
    int wid = tid >> 5;
#pragma unroll
    for (int i = tid; i < 8 * 256; i += THREADS) ((int*)sh)[i] = 0;
    __syncthreads();

    float minv = dec_f(d_umin), maxv = dec_f(d_umax);
    float range = maxv - minv;
    if (range == 0.0f) range = 1.0f;

    int base = blockIdx.x * SEG;
#pragma unroll
    for (int k = 0; k < SEG; k += THREADS * 4) {
        int idx = base + k + tid * 4;
        if (idx + 3 < n) {
            float4 v = *reinterpret_cast<const float4*>(x + idx);
            int q0 = quant(v.x, minv, range);
            int q1 = quant(v.y, minv, range);
            int q2 = quant(v.z, minv, range);
            int q3 = quant(v.w, minv, range);
            atomicAdd(&sh[wid][q0], 1);
            atomicAdd(&sh[wid][q1], 1);
            atomicAdd(&sh[wid][q2], 1);
            atomicAdd(&sh[wid][q3], 1);
            uchar4 qc;
            qc.x = (unsigned char)q0; qc.y = (unsigned char)q1;
            qc.z = (unsigned char)q2; qc.w = (unsigned char)q3;
            *reinterpret_cast<uchar4*>(d_qbuf + idx) = qc;
        } else {
            for (int m = 0; m < 4; m++) {
                int j = idx + m;
                if (j < n) {
                    int q = quant(x[j], minv, range);
                    atomicAdd(&sh[wid][q], 1);
                    d_qbuf[j] = (unsigned char)q;
                }
            }
        }
    }
    __syncthreads();
    int tot = 0;
#pragma unroll
    for (int w = 0; w < 8; w++) tot += sh[w][tid];
    atomicAdd(&d_hist[tid], tot);
    d_bhT[tid][blockIdx.x] = tot;     // bin-major: column t is contiguous
}

// ---------------- pass 3: threshold + tie-offset scan (1024 threads) -------
__global__ void k_select(int nb, int keep) {
    __shared__ int sc[256];
    __shared__ int s_t;
    __shared__ int wsum[32];
    int tid = threadIdx.x;
    int lane = tid & 31, wid = tid >> 5;

    // -- phase A: suffix scan over 256 bins (threads 0..255 active) --
    int h = 0;
    if (tid < 256) { h = d_hist[tid]; sc[tid] = h; }
    __syncthreads();
#pragma unroll
    for (int off = 1; off < 256; off <<= 1) {
        int add = 0;
        if (tid < 256 && tid + off < 256) add = sc[tid + off];
        __syncthreads();
        if (tid < 256) sc[tid] += add;
        __syncthreads();
    }
    if (tid < 256) {
        int ge = sc[tid];
        int gt = ge - h;
        if (gt < keep && ge >= keep) {   // exactly one bin satisfies this
            d_t = tid;
            d_r = keep - gt;
            s_t = tid;
        }
        d_hist[tid] = 0;                 // re-arm for next run
    }
    __syncthreads();
    int t = s_t;

    // -- phase B: exclusive prefix scan of d_bhT[t][0..nb) (contiguous) --
    const int* col = d_bhT[t];
    int i0 = 2 * tid, i1 = 2 * tid + 1;
    int a = (i0 < nb) ? col[i0] : 0;
    int b = (i1 < nb) ? col[i1] : 0;
    int s = a + b;
    int x = s;
#pragma unroll
    for (int o = 1; o < 32; o <<= 1) {
        int y = __shfl_up_sync(0xFFFFFFFFu, x, o);
        if (lane >= o) x += y;
    }
    if (lane == 31) wsum[wid] = x;
    __syncthreads();
    if (tid < 32) {
        int w = wsum[tid];
#pragma unroll
        for (int o = 1; o < 32; o <<= 1) {
            int y = __shfl_up_sync(0xFFFFFFFFu, w, o);
            if (tid >= o) w += y;
        }
        wsum[tid] = w;
    }
    __syncthreads();
    int incl = x + (wid ? wsum[wid - 1] : 0);
    int excl = incl - s;
    if (i0 < nb) d_tieoff[i0] = excl;
    if (i1 < nb) d_tieoff[i1] = excl + a;
}

// ---------------- pass 4: write sparsified output (warp-chunked) ----------
// Warp w owns elements [blockbase + w*1024, +1024), 8 lane-strided rounds.
// Index order == (warp, round, lane, elem) order -> ranks need only warp
// scans (shfl) + ONE block barrier to combine warp totals.
__global__ void k_output(float* __restrict__ out, int n, long long out_n) {
    int tid = threadIdx.x;
    int lane = tid & 31, wid = tid >> 5;
    int t = d_t, r = d_r;

    __shared__ int s_wtot[8];

    int blockbase = blockIdx.x * SEG;
    int warpbase = blockbase + wid * 1024;

    uchar4 qc[8];
    unsigned int vm[8];
    int excl[8], prior[8];
    int run = 0;

#pragma unroll
    for (int rr = 0; rr < 8; rr++) {
        int idx = warpbase + rr * 128 + lane * 4;
        uchar4 q = make_uchar4(0, 0, 0, 0);
        unsigned int m = 0;
        if (idx + 3 < n) {
            q = *reinterpret_cast<const uchar4*>(d_qbuf + idx);
            m = 0xFu;
        } else {
            if (idx + 0 < n) { q.x = d_qbuf[idx + 0]; m |= 1u; }
            if (idx + 1 < n) { q.y = d_qbuf[idx + 1]; m |= 2u; }
            if (idx + 2 < n) { q.z = d_qbuf[idx + 2]; m |= 4u; }
        }
        qc[rr] = q; vm[rr] = m;
        int cnt = (((m & 1u) && q.x == t) ? 1 : 0) +
                  (((m & 2u) && q.y == t) ? 1 : 0) +
                  (((m & 4u) && q.z == t) ? 1 : 0) +
                  (((m & 8u) && q.w == t) ? 1 : 0);
        int x = cnt;
#pragma unroll
        for (int o = 1; o < 32; o <<= 1) {
            int y = __shfl_up_sync(0xFFFFFFFFu, x, o);
            if (lane >= o) x += y;
        }
        excl[rr]  = x - cnt;                 // intra-round exclusive prefix
        prior[rr] = run;                     // ties in earlier rounds
        run += __shfl_sync(0xFFFFFFFFu, x, 31);
    }
    if (lane == 0) s_wtot[wid] = run;
    __syncthreads();

    int wbase = d_tieoff[blockIdx.x];
#pragma unroll
    for (int w = 0; w < 8; w++)
        if (w < wid) wbase += s_wtot[w];

#pragma unroll
    for (int rr = 0; rr < 8; rr++) {
        int idx = warpbase + rr * 128 + lane * 4;
        if (idx >= n) continue;
        uchar4 q = qc[rr];
        unsigned int m = vm[rr];
        int rank = wbase + prior[rr] + excl[rr];

        float o0, o1, o2, o3;
        if (q.x > t) o0 = (float)q.x; else if ((m & 1u) && q.x == t) { o0 = (rank < r) ? (float)q.x : 0.0f; rank++; } else o0 = 0.0f;
        if (q.y > t) o1 = (float)q.y; else if ((m & 2u) && q.y == t) { o1 = (rank < r) ? (float)q.y : 0.0f; rank++; } else o1 = 0.0f;
        if (q.z > t) o2 = (float)q.z; else if ((m & 4u) && q.z == t) { o2 = (rank < r) ? (float)q.z : 0.0f; rank++; } else o2 = 0.0f;
        if (q.w > t) o3 = (float)q.w; else if ((m & 8u) && q.w == t) { o3 = (rank < r) ? (float)q.w : 0.0f; rank++; } else o3 = 0.0f;

        if (m == 0xFu) {
            float4 ov; ov.x = o0; ov.y = o1; ov.z = o2; ov.w = o3;
            *reinterpret_cast<float4*>(out + idx) = ov;
        } else {
            if (m & 1u) out[idx + 0] = o0;
            if (m & 2u) out[idx + 1] = o1;
            if (m & 4u) out[idx + 2] = o2;
        }
    }

    if (blockIdx.x == 0 && tid == 0) {
        float minv = dec_f(d_umin), maxv = dec_f(d_umax);
        float range = maxv - minv;
        if (range == 0.0f) range = 1.0f;
        if (out_n >= (long long)n + 3) {
            out[n + 0] = minv;
            out[n + 1] = maxv;
            out[n + 2] = range;
        }
        // re-arm min/max for the next graph replay
        d_umin = 0xFFFFFFFFu;
        d_umax = 0u;
    }
}

// ---------------- launch ----------------
extern "C" void kernel_launch(void* const* d_in, const int* in_sizes, int n_in,
                              void* d_out, int out_size) {
    const float* x = (const float*)d_in[0];
    float* out = (float*)d_out;
    int n = in_sizes[0];
    int nb = (n + SEG - 1) / SEG;            // 2048 for 2^24
    int keep = (int)((double)n * 0.5);       // int(total * (1 - SPARSE_RATIO))

    k_minmax<<<2048, THREADS>>>(x, n);
    k_quanthist<<<nb, THREADS>>>(x, n);
    k_select<<<1, 1024>>>(nb, keep);
    k_output<<<nb, THREADS>>>(out, n, (long long)out_size);
}

// round 4
// speedup vs baseline: 1.3251x; 1.3251x over previous
#include <cuda_runtime.h>
#include <math_constants.h>

#define THREADS 256
#define SEG 8192              // elements per block in quant/output passes
#define MAXB 4096
#define NELEM_MAX (1 << 24)   // 1*32*4096*128 = 2^24

// ---------------- device scratch (no allocations allowed) ----------------
__device__ unsigned int d_umin = 0xFFFFFFFFu;   // re-armed at end of k_output
__device__ unsigned int d_umax = 0u;
__device__ int d_hist[256];                     // zeroed at end of k_select
__device__ int d_bhT[256][MAXB];                // bin-major per-block histogram
__device__ unsigned char d_qbuf[NELEM_MAX];
__device__ int d_t, d_r;
__device__ int d_tieoff[MAXB];

// order-preserving float <-> uint mapping for atomic min/max
__device__ __forceinline__ unsigned int enc_f(float f) {
    unsigned int u = __float_as_uint(f);
    return (u & 0x80000000u) ? ~u : (u | 0x80000000u);
}
__device__ __forceinline__ float dec_f(unsigned int e) {
    unsigned int u = (e & 0x80000000u) ? (e & 0x7FFFFFFFu) : ~e;
    return __uint_as_float(u);
}

// exact quantization matching jnp: ((x-min)/range)*255, round-half-even
__device__ __forceinline__ int quant(float v, float minv, float range) {
    float n = __fdiv_rn(v - minv, range);       // IEEE divide (no fast-math)
    float s = __fmul_rn(n, 255.0f);             // IEEE multiply
    int q = (int)rintf(s);                      // RNE, same as jnp.round
    return min(255, max(0, q));
}

// ---------------- pass 1: global min/max ----------------
__global__ void k_minmax(const float* __restrict__ x, int n) {
    float lmin = CUDART_INF_F, lmax = -CUDART_INF_F;
    int n4 = n >> 2;
    const float4* x4 = reinterpret_cast<const float4*>(x);
    for (int i = blockIdx.x * blockDim.x + threadIdx.x; i < n4;
         i += gridDim.x * blockDim.x) {
        float4 v = x4[i];
        lmin = fminf(lmin, fminf(fminf(v.x, v.y), fminf(v.z, v.w)));
        lmax = fmaxf(lmax, fmaxf(fmaxf(v.x, v.y), fmaxf(v.z, v.w)));
    }
    if (blockIdx.x == 0) {  // scalar tail
        for (int i = n4 * 4 + threadIdx.x; i < n; i += blockDim.x) {
            float v = x[i];
            lmin = fminf(lmin, v);
            lmax = fmaxf(lmax, v);
        }
    }
#pragma unroll
    for (int o = 16; o; o >>= 1) {
        lmin = fminf(lmin, __shfl_xor_sync(0xFFFFFFFFu, lmin, o));
        lmax = fmaxf(lmax, __shfl_xor_sync(0xFFFFFFFFu, lmax, o));
    }
    __shared__ float smin[8], smax[8];
    int lane = threadIdx.x & 31, wid = threadIdx.x >> 5;
    if (lane == 0) { smin[wid] = lmin; smax[wid] = lmax; }
    __syncthreads();
    if (threadIdx.x == 0) {
#pragma unroll
        for (int w = 1; w < 8; w++) {
            lmin = fminf(lmin, smin[w]);
            lmax = fmaxf(lmax, smax[w]);
        }
        atomicMin(&d_umin, enc_f(lmin));
        atomicMax(&d_umax, enc_f(lmax));
    }
}

// ---------------- pass 2: quantize + per-block histogram ----------------
__global__ void k_quanthist(const float* __restrict__ x, int n) {
    __shared__ int sh[8][256];   // per-warp sub-histograms (8 KB)
    int tid = threadIdx.x;
    int wid = tid >> 5;
#pragma unroll
    for (int i = tid; i < 8 * 256; i += THREADS) ((int*)sh)[i] = 0;
    __syncthreads();

    float minv = dec_f(d_umin), maxv = dec_f(d_umax);
    float range = maxv - minv;
    if (range == 0.0f) range = 1.0f;

    int base = blockIdx.x * SEG;
#pragma unroll
    for (int k = 0; k < SEG; k += THREADS * 4) {
        int idx = base + k + tid * 4;
        if (idx + 3 < n) {
            float4 v = *reinterpret_cast<const float4*>(x + idx);
            int q0 = quant(v.x, minv, range);
            int q1 = quant(v.y, minv, range);
            int q2 = quant(v.z, minv, range);
            int q3 = quant(v.w, minv, range);
            atomicAdd(&sh[wid][q0], 1);
            atomicAdd(&sh[wid][q1], 1);
            atomicAdd(&sh[wid][q2], 1);
            atomicAdd(&sh[wid][q3], 1);
            uchar4 qc;
            qc.x = (unsigned char)q0; qc.y = (unsigned char)q1;
            qc.z = (unsigned char)q2; qc.w = (unsigned char)q3;
            *reinterpret_cast<uchar4*>(d_qbuf + idx) = qc;
        } else {
            for (int m = 0; m < 4; m++) {
                int j = idx + m;
                if (j < n) {
                    int q = quant(x[j], minv, range);
                    atomicAdd(&sh[wid][q], 1);
                    d_qbuf[j] = (unsigned char)q;
                }
            }
        }
    }
    __syncthreads();
    int tot = 0;
#pragma unroll
    for (int w = 0; w < 8; w++) tot += sh[w][tid];
    atomicAdd(&d_hist[tid], tot);
    d_bhT[tid][blockIdx.x] = tot;     // bin-major: column t is contiguous
}

// ---------------- pass 3: threshold + tie-offset scan (1024 threads) -------
__global__ void k_select(int nb, int keep) {
    __shared__ int sc[256];
    __shared__ int s_t;
    __shared__ int wsum[32];
    int tid = threadIdx.x;
    int lane = tid & 31, wid = tid >> 5;

    // -- phase A: suffix scan over 256 bins (threads 0..255 active) --
    int h = 0;
    if (tid < 256) { h = d_hist[tid]; sc[tid] = h; }
    __syncthreads();
#pragma unroll
    for (int off = 1; off < 256; off <<= 1) {
        int add = 0;
        if (tid < 256 && tid + off < 256) add = sc[tid + off];
        __syncthreads();
        if (tid < 256) sc[tid] += add;
        __syncthreads();
    }
    if (tid < 256) {
        int ge = sc[tid];
        int gt = ge - h;
        if (gt < keep && ge >= keep) {   // exactly one bin satisfies this
            d_t = tid;
            d_r = keep - gt;
            s_t = tid;
        }
        d_hist[tid] = 0;                 // re-arm for next run
    }
    __syncthreads();
    int t = s_t;

    // -- phase B: exclusive prefix scan of d_bhT[t][0..nb) (contiguous) --
    const int* col = d_bhT[t];
    int i0 = 2 * tid, i1 = 2 * tid + 1;
    int a = (i0 < nb) ? col[i0] : 0;
    int b = (i1 < nb) ? col[i1] : 0;
    int s = a + b;
    int x = s;
#pragma unroll
    for (int o = 1; o < 32; o <<= 1) {
        int y = __shfl_up_sync(0xFFFFFFFFu, x, o);
        if (lane >= o) x += y;
    }
    if (lane == 31) wsum[wid] = x;
    __syncthreads();
    if (tid < 32) {
        int w = wsum[tid];
#pragma unroll
        for (int o = 1; o < 32; o <<= 1) {
            int y = __shfl_up_sync(0xFFFFFFFFu, w, o);
            if (tid >= o) w += y;
        }
        wsum[tid] = w;
    }
    __syncthreads();
    int incl = x + (wid ? wsum[wid - 1] : 0);
    int excl = incl - s;
    if (i0 < nb) d_tieoff[i0] = excl;
    if (i1 < nb) d_tieoff[i1] = excl + a;
}

// ---------------- pass 4: write sparsified output ----------------
// Warp w owns elements [blockbase + w*1024, +1024) in 8 lane-strided rounds
// (index order == (warp, round, lane, byte)). Two phases:
//   phase 1: ballot-count ties per warp (no scans, no register arrays)
//   phase 2: re-load q (L1-hit), ballot-rank, write float4
// Exactly ONE __syncthreads in the whole kernel.
__global__ void k_output(float* __restrict__ out, int n, long long out_n) {
    int tid = threadIdx.x;
    int lane = tid & 31, wid = tid >> 5;
    int t = d_t, r = d_r;

    __shared__ int s_wtot[8];
    unsigned int ltmask = (1u << lane) - 1u;

    int warpbase = blockIdx.x * SEG + wid * 1024;

    // ---- phase 1: per-warp tie count ----
    int wcnt = 0;
#pragma unroll
    for (int rr = 0; rr < 8; rr++) {
        int idx = warpbase + rr * 128 + lane * 4;
        uchar4 q = make_uchar4(255, 255, 255, 255);   // OOB: never ties unless t==255
        unsigned int m = 0;
        if (idx + 3 < n) {
            q = *reinterpret_cast<const uchar4*>(d_qbuf + idx);
            m = 0xFu;
        } else {
            if (idx + 0 < n) { q.x = d_qbuf[idx + 0]; m |= 1u; }
            if (idx + 1 < n) { q.y = d_qbuf[idx + 1]; m |= 2u; }
            if (idx + 2 < n) { q.z = d_qbuf[idx + 2]; m |= 4u; }
        }
        unsigned int b0 = __ballot_sync(0xFFFFFFFFu, (m & 1u) && q.x == t);
        unsigned int b1 = __ballot_sync(0xFFFFFFFFu, (m & 2u) && q.y == t);
        unsigned int b2 = __ballot_sync(0xFFFFFFFFu, (m & 4u) && q.z == t);
        unsigned int b3 = __ballot_sync(0xFFFFFFFFu, (m & 8u) && q.w == t);
        wcnt += __popc(b0) + __popc(b1) + __popc(b2) + __popc(b3);
    }
    if (lane == 0) s_wtot[wid] = wcnt;
    __syncthreads();

    int wbase = d_tieoff[blockIdx.x];
#pragma unroll
    for (int w = 0; w < 8; w++)
        if (w < wid) wbase += s_wtot[w];

    // ---- phase 2: rank + write (q re-loads hit L1) ----
    int run = 0;
#pragma unroll
    for (int rr = 0; rr < 8; rr++) {
        int idx = warpbase + rr * 128 + lane * 4;
        uchar4 q = make_uchar4(255, 255, 255, 255);
        unsigned int m = 0;
        if (idx + 3 < n) {
            q = *reinterpret_cast<const uchar4*>(d_qbuf + idx);
            m = 0xFu;
        } else {
            if (idx + 0 < n) { q.x = d_qbuf[idx + 0]; m |= 1u; }
            if (idx + 1 < n) { q.y = d_qbuf[idx + 1]; m |= 2u; }
            if (idx + 2 < n) { q.z = d_qbuf[idx + 2]; m |= 4u; }
        }
        bool t0 = (m & 1u) && q.x == t;
        bool t1 = (m & 2u) && q.y == t;
        bool t2 = (m & 4u) && q.z == t;
        bool t3 = (m & 8u) && q.w == t;
        unsigned int b0 = __ballot_sync(0xFFFFFFFFu, t0);
        unsigned int b1 = __ballot_sync(0xFFFFFFFFu, t1);
        unsigned int b2 = __ballot_sync(0xFFFFFFFFu, t2);
        unsigned int b3 = __ballot_sync(0xFFFFFFFFu, t3);
        // ties ahead of this lane within the round (order: lane-major, byte-minor)
        int before = __popc(b0 & ltmask) + __popc(b1 & ltmask) +
                     __popc(b2 & ltmask) + __popc(b3 & ltmask);
        int rank = wbase + run + before;
        run += __popc(b0) + __popc(b1) + __popc(b2) + __popc(b3);

        if (m == 0) continue;

        float o0, o1, o2, o3;
        if (q.x > t) o0 = (float)q.x; else if (t0) { o0 = (rank < r) ? (float)q.x : 0.0f; rank++; } else o0 = 0.0f;
        if (q.y > t) o1 = (float)q.y; else if (t1) { o1 = (rank < r) ? (float)q.y : 0.0f; rank++; } else o1 = 0.0f;
        if (q.z > t) o2 = (float)q.z; else if (t2) { o2 = (rank < r) ? (float)q.z : 0.0f; rank++; } else o2 = 0.0f;
        if (q.w > t) o3 = (float)q.w; else if (t3) { o3 = (rank < r) ? (float)q.w : 0.0f; rank++; } else o3 = 0.0f;

        if (m == 0xFu) {
            float4 ov; ov.x = o0; ov.y = o1; ov.z = o2; ov.w = o3;
            *reinterpret_cast<float4*>(out + idx) = ov;
        } else {
            if (m & 1u) out[idx + 0] = o0;
            if (m & 2u) out[idx + 1] = o1;
            if (m & 4u) out[idx + 2] = o2;
        }
    }

    if (blockIdx.x == 0 && tid == 0) {
        float minv = dec_f(d_umin), maxv = dec_f(d_umax);
        float range = maxv - minv;
        if (range == 0.0f) range = 1.0f;
        if (out_n >= (long long)n + 3) {
            out[n + 0] = minv;
            out[n + 1] = maxv;
            out[n + 2] = range;
        }
        // re-arm min/max for the next graph replay
        d_umin = 0xFFFFFFFFu;
        d_umax = 0u;
    }
}

// ---------------- launch ----------------
extern "C" void kernel_launch(void* const* d_in, const int* in_sizes, int n_in,
                              void* d_out, int out_size) {
    const float* x = (const float*)d_in[0];
    float* out = (float*)d_out;
    int n = in_sizes[0];
    int nb = (n + SEG - 1) / SEG;            // 2048 for 2^24
    int keep = (int)((double)n * 0.5);       // int(total * (1 - SPARSE_RATIO))

    k_minmax<<<2048, THREADS>>>(x, n);
    k_quanthist<<<nb, THREADS>>>(x, n);
    k_select<<<1, 1024>>>(nb, keep);
    k_output<<<nb, THREADS>>>(out, n, (long long)out_size);
}

// round 5
// speedup vs baseline: 1.6046x; 1.2109x over previous
#include <cuda_runtime.h>
#include <math_constants.h>

#define THREADS 256
#define SEG 8192              // elements per block in quant/output passes
#define MAXB 4096
#define NELEM_MAX (1 << 24)   // 1*32*4096*128 = 2^24

// ---------------- device scratch (no allocations allowed) ----------------
__device__ unsigned int d_umin = 0xFFFFFFFFu;   // re-armed at end of k_output
__device__ unsigned int d_umax = 0u;
__device__ int d_hist[256];                     // zeroed at end of k_select
__device__ int d_bhT[256][MAXB];                // bin-major per-block histogram
__device__ unsigned char d_qbuf[NELEM_MAX];
__device__ int d_t, d_r;
__device__ int d_tieoff[MAXB + 1];              // [b]=excl prefix, [nb]=total

// order-preserving float <-> uint mapping for atomic min/max
__device__ __forceinline__ unsigned int enc_f(float f) {
    unsigned int u = __float_as_uint(f);
    return (u & 0x80000000u) ? ~u : (u | 0x80000000u);
}
__device__ __forceinline__ float dec_f(unsigned int e) {
    unsigned int u = (e & 0x80000000u) ? (e & 0x7FFFFFFFu) : ~e;
    return __uint_as_float(u);
}

// exact quantization matching jnp: ((x-min)/range)*255, round-half-even
__device__ __forceinline__ int quant(float v, float minv, float range) {
    float n = __fdiv_rn(v - minv, range);       // IEEE divide (no fast-math)
    float s = __fmul_rn(n, 255.0f);             // IEEE multiply
    int q = (int)rintf(s);                      // RNE, same as jnp.round
    return min(255, max(0, q));
}

// ---------------- pass 1: global min/max ----------------
__global__ void k_minmax(const float* __restrict__ x, int n) {
    float lmin = CUDART_INF_F, lmax = -CUDART_INF_F;
    int n4 = n >> 2;
    const float4* x4 = reinterpret_cast<const float4*>(x);
    for (int i = blockIdx.x * blockDim.x + threadIdx.x; i < n4;
         i += gridDim.x * blockDim.x) {
        float4 v = x4[i];
        lmin = fminf(lmin, fminf(fminf(v.x, v.y), fminf(v.z, v.w)));
        lmax = fmaxf(lmax, fmaxf(fmaxf(v.x, v.y), fmaxf(v.z, v.w)));
    }
    if (blockIdx.x == 0) {  // scalar tail
        for (int i = n4 * 4 + threadIdx.x; i < n; i += blockDim.x) {
            float v = x[i];
            lmin = fminf(lmin, v);
            lmax = fmaxf(lmax, v);
        }
    }
#pragma unroll
    for (int o = 16; o; o >>= 1) {
        lmin = fminf(lmin, __shfl_xor_sync(0xFFFFFFFFu, lmin, o));
        lmax = fmaxf(lmax, __shfl_xor_sync(0xFFFFFFFFu, lmax, o));
    }
    __shared__ float smin[8], smax[8];
    int lane = threadIdx.x & 31, wid = threadIdx.x >> 5;
    if (lane == 0) { smin[wid] = lmin; smax[wid] = lmax; }
    __syncthreads();
    if (threadIdx.x == 0) {
#pragma unroll
        for (int w = 1; w < 8; w++) {
            lmin = fminf(lmin, smin[w]);
            lmax = fmaxf(lmax, smax[w]);
        }
        atomicMin(&d_umin, enc_f(lmin));
        atomicMax(&d_umax, enc_f(lmax));
    }
}

// ---------------- pass 2: quantize + per-block histogram ----------------
__global__ void k_quanthist(const float* __restrict__ x, int n) {
    __shared__ int sh[8][256];   // per-warp sub-histograms (8 KB)
    int tid = threadIdx.x;
    int wid = tid >> 5;
#pragma unroll
    for (int i = tid; i < 8 * 256; i += THREADS) ((int*)sh)[i] = 0;
    __syncthreads();

    float minv = dec_f(d_umin), maxv = dec_f(d_umax);
    float range = maxv - minv;
    if (range == 0.0f) range = 1.0f;

    int base = blockIdx.x * SEG;
#pragma unroll
    for (int k = 0; k < SEG; k += THREADS * 4) {
        int idx = base + k + tid * 4;
        if (idx + 3 < n) {
            float4 v = *reinterpret_cast<const float4*>(x + idx);
            int q0 = quant(v.x, minv, range);
            int q1 = quant(v.y, minv, range);
            int q2 = quant(v.z, minv, range);
            int q3 = quant(v.w, minv, range);
            atomicAdd(&sh[wid][q0], 1);
            atomicAdd(&sh[wid][q1], 1);
            atomicAdd(&sh[wid][q2], 1);
            atomicAdd(&sh[wid][q3], 1);
            uchar4 qc;
            qc.x = (unsigned char)q0; qc.y = (unsigned char)q1;
            qc.z = (unsigned char)q2; qc.w = (unsigned char)q3;
            *reinterpret_cast<uchar4*>(d_qbuf + idx) = qc;
        } else {
            for (int m = 0; m < 4; m++) {
                int j = idx + m;
                if (j < n) {
                    int q = quant(x[j], minv, range);
                    atomicAdd(&sh[wid][q], 1);
                    d_qbuf[j] = (unsigned char)q;
                }
            }
        }
    }
    __syncthreads();
    int tot = 0;
#pragma unroll
    for (int w = 0; w < 8; w++) tot += sh[w][tid];
    atomicAdd(&d_hist[tid], tot);
    d_bhT[tid][blockIdx.x] = tot;     // bin-major: column t is contiguous
}

// ---------------- pass 3: threshold + tie-offset scan (1024 threads) -------
__global__ void k_select(int nb, int keep) {
    __shared__ int sc[256];
    __shared__ int s_t;
    __shared__ int wsum[32];
    int tid = threadIdx.x;
    int lane = tid & 31, wid = tid >> 5;

    // -- phase A: suffix scan over 256 bins (threads 0..255 active) --
    int h = 0;
    if (tid < 256) { h = d_hist[tid]; sc[tid] = h; }
    __syncthreads();
#pragma unroll
    for (int off = 1; off < 256; off <<= 1) {
        int add = 0;
        if (tid < 256 && tid + off < 256) add = sc[tid + off];
        __syncthreads();
        if (tid < 256) sc[tid] += add;
        __syncthreads();
    }
    if (tid < 256) {
        int ge = sc[tid];
        int gt = ge - h;
        if (gt < keep && ge >= keep) {   // exactly one bin satisfies this
            d_t = tid;
            d_r = keep - gt;
            s_t = tid;
        }
        d_hist[tid] = 0;                 // re-arm for next run
    }
    __syncthreads();
    int t = s_t;

    // -- phase B: exclusive prefix scan of d_bhT[t][0..nb) (contiguous) --
    const int* col = d_bhT[t];
    int i0 = 2 * tid, i1 = 2 * tid + 1;
    int a = (i0 < nb) ? col[i0] : 0;
    int b = (i1 < nb) ? col[i1] : 0;
    int s = a + b;
    int x = s;
#pragma unroll
    for (int o = 1; o < 32; o <<= 1) {
        int y = __shfl_up_sync(0xFFFFFFFFu, x, o);
        if (lane >= o) x += y;
    }
    if (lane == 31) wsum[wid] = x;
    __syncthreads();
    if (tid < 32) {
        int w = wsum[tid];
#pragma unroll
        for (int o = 1; o < 32; o <<= 1) {
            int y = __shfl_up_sync(0xFFFFFFFFu, w, o);
            if (tid >= o) w += y;
        }
        wsum[tid] = w;
    }
    __syncthreads();
    int incl = x + (wid ? wsum[wid - 1] : 0);
    int excl = incl - s;
    if (i0 < nb) d_tieoff[i0] = excl;
    if (i1 < nb) d_tieoff[i1] = excl + a;
    if (tid == 0) d_tieoff[nb] = wsum[31];   // total ties
}

// ---------------- pass 4: write sparsified output ----------------
// Tie-ranks are monotone in block order, so a block keeps ALL its ties
// (e<=r), NONE (s>=r), or is the single straddling block that needs real
// intra-block ranking. Fast path = pure streaming, no scans/barriers.
__global__ void k_output(float* __restrict__ out, int n, long long out_n) {
    int tid = threadIdx.x;
    int lane = tid & 31, wid = tid >> 5;
    int t = d_t, r = d_r;
    int b = blockIdx.x;
    int s = d_tieoff[b], e = d_tieoff[b + 1];

    int warpbase = b * SEG + wid * 1024;

    if (e <= r || s >= r) {
        // ---- fast path: keep q >= keepv ----
        int keepv = (e <= r) ? t : (t + 1);
#pragma unroll
        for (int rr = 0; rr < 8; rr++) {
            int idx = warpbase + rr * 128 + lane * 4;
            if (idx + 3 < n) {
                uchar4 q = *reinterpret_cast<const uchar4*>(d_qbuf + idx);
                float4 ov;
                ov.x = (q.x >= keepv) ? (float)q.x : 0.0f;
                ov.y = (q.y >= keepv) ? (float)q.y : 0.0f;
                ov.z = (q.z >= keepv) ? (float)q.z : 0.0f;
                ov.w = (q.w >= keepv) ? (float)q.w : 0.0f;
                *reinterpret_cast<float4*>(out + idx) = ov;
            } else {
                for (int m = 0; m < 4; m++) {
                    int j = idx + m;
                    if (j < n) {
                        int q = d_qbuf[j];
                        out[j] = (q >= keepv) ? (float)q : 0.0f;
                    }
                }
            }
        }
    } else {
        // ---- partial path: exactly one block — two-phase ballot ranking ----
        __shared__ int s_wtot[8];
        unsigned int ltmask = (1u << lane) - 1u;

        int wcnt = 0;
#pragma unroll
        for (int rr = 0; rr < 8; rr++) {
            int idx = warpbase + rr * 128 + lane * 4;
            uchar4 q = make_uchar4(255, 255, 255, 255);
            unsigned int m = 0;
            if (idx + 3 < n) {
                q = *reinterpret_cast<const uchar4*>(d_qbuf + idx);
                m = 0xFu;
            } else {
                if (idx + 0 < n) { q.x = d_qbuf[idx + 0]; m |= 1u; }
                if (idx + 1 < n) { q.y = d_qbuf[idx + 1]; m |= 2u; }
                if (idx + 2 < n) { q.z = d_qbuf[idx + 2]; m |= 4u; }
            }
            unsigned int b0 = __ballot_sync(0xFFFFFFFFu, (m & 1u) && q.x == t);
            unsigned int b1 = __ballot_sync(0xFFFFFFFFu, (m & 2u) && q.y == t);
            unsigned int b2 = __ballot_sync(0xFFFFFFFFu, (m & 4u) && q.z == t);
            unsigned int b3 = __ballot_sync(0xFFFFFFFFu, (m & 8u) && q.w == t);
            wcnt += __popc(b0) + __popc(b1) + __popc(b2) + __popc(b3);
        }
        if (lane == 0) s_wtot[wid] = wcnt;
        __syncthreads();

        int wbase = s;
#pragma unroll
        for (int w = 0; w < 8; w++)
            if (w < wid) wbase += s_wtot[w];

        int run = 0;
#pragma unroll
        for (int rr = 0; rr < 8; rr++) {
            int idx = warpbase + rr * 128 + lane * 4;
            uchar4 q = make_uchar4(255, 255, 255, 255);
            unsigned int m = 0;
            if (idx + 3 < n) {
                q = *reinterpret_cast<const uchar4*>(d_qbuf + idx);
                m = 0xFu;
            } else {
                if (idx + 0 < n) { q.x = d_qbuf[idx + 0]; m |= 1u; }
                if (idx + 1 < n) { q.y = d_qbuf[idx + 1]; m |= 2u; }
                if (idx + 2 < n) { q.z = d_qbuf[idx + 2]; m |= 4u; }
            }
            bool t0 = (m & 1u) && q.x == t;
            bool t1 = (m & 2u) && q.y == t;
            bool t2 = (m & 4u) && q.z == t;
            bool t3 = (m & 8u) && q.w == t;
            unsigned int b0 = __ballot_sync(0xFFFFFFFFu, t0);
            unsigned int b1 = __ballot_sync(0xFFFFFFFFu, t1);
            unsigned int b2 = __ballot_sync(0xFFFFFFFFu, t2);
            unsigned int b3 = __ballot_sync(0xFFFFFFFFu, t3);
            int before = __popc(b0 & ltmask) + __popc(b1 & ltmask) +
                         __popc(b2 & ltmask) + __popc(b3 & ltmask);
            int rank = wbase + run + before;
            run += __popc(b0) + __popc(b1) + __popc(b2) + __popc(b3);

            if (m == 0) continue;

            float o0, o1, o2, o3;
            if (q.x > t) o0 = (float)q.x; else if (t0) { o0 = (rank < r) ? (float)q.x : 0.0f; rank++; } else o0 = 0.0f;
            if (q.y > t) o1 = (float)q.y; else if (t1) { o1 = (rank < r) ? (float)q.y : 0.0f; rank++; } else o1 = 0.0f;
            if (q.z > t) o2 = (float)q.z; else if (t2) { o2 = (rank < r) ? (float)q.z : 0.0f; rank++; } else o2 = 0.0f;
            if (q.w > t) o3 = (float)q.w; else if (t3) { o3 = (rank < r) ? (float)q.w : 0.0f; rank++; } else o3 = 0.0f;

            if (m == 0xFu) {
                float4 ov; ov.x = o0; ov.y = o1; ov.z = o2; ov.w = o3;
                *reinterpret_cast<float4*>(out + idx) = ov;
            } else {
                if (m & 1u) out[idx + 0] = o0;
                if (m & 2u) out[idx + 1] = o1;
                if (m & 4u) out[idx + 2] = o2;
            }
        }
    }

    if (b == 0 && tid == 0) {
        float minv = dec_f(d_umin), maxv = dec_f(d_umax);
        float range = maxv - minv;
        if (range == 0.0f) range = 1.0f;
        if (out_n >= (long long)n + 3) {
            out[n + 0] = minv;
            out[n + 1] = maxv;
            out[n + 2] = range;
        }
        // re-arm min/max for the next graph replay
        d_umin = 0xFFFFFFFFu;
        d_umax = 0u;
    }
}

// ---------------- launch ----------------
extern "C" void kernel_launch(void* const* d_in, const int* in_sizes, int n_in,
                              void* d_out, int out_size) {
    const float* x = (const float*)d_in[0];
    float* out = (float*)d_out;
    int n = in_sizes[0];
    int nb = (n + SEG - 1) / SEG;            // 2048 for 2^24
    int keep = (int)((double)n * 0.5);       // int(total * (1 - SPARSE_RATIO))

    k_minmax<<<2048, THREADS>>>(x, n);
    k_quanthist<<<nb, THREADS>>>(x, n);
    k_select<<<1, 1024>>>(nb, keep);
    k_output<<<nb, THREADS>>>(out, n, (long long)out_size);
}